// round 14
// baseline (speedup 1.0000x reference)
#include <cuda_runtime.h>
#include <cuda_fp16.h>
#include <cstdint>

#define B_  4
#define S_  2048
#define D_  1024
#define H_  16
#define DK_ 64
#define M_  (B_*S_)

// ---------------------------------------------------------------------------
// Scratch (fp16 bit-patterns in ushort arrays; no allocation APIs)
// ---------------------------------------------------------------------------
__device__ unsigned short c_qh[M_*D_], c_ql[M_*D_];
__device__ unsigned short c_kh[M_*D_], c_kl[M_*D_];
__device__ unsigned short c_vh[M_*D_], c_vl[M_*D_];
__device__ unsigned short w_qh[D_*D_], w_ql[D_*D_];
__device__ unsigned short w_kh[D_*D_], w_kl[D_*D_];
__device__ unsigned short w_vh[D_*D_], w_vl[D_*D_];
__device__ unsigned short w_oh[D_*D_], w_ol[D_*D_];
__device__ unsigned short p_qh[M_*D_], p_ql[M_*D_];   // Q proj, [bh][s][dk]
__device__ unsigned short p_kh[M_*D_], p_kl[M_*D_];   // K proj, [bh][s][dk]
__device__ unsigned short p_vth[M_*D_], p_vtl[M_*D_]; // V proj, [bh][dk][s]
__device__ unsigned short x_h[M_*D_], x_l[M_*D_];     // attn out, [b][s][d]
__device__ unsigned int   m_bits[S_*S_/32];           // mask bitmask

// ---------------------------------------------------------------------------
// Helpers
// ---------------------------------------------------------------------------
__device__ __forceinline__ uint32_t smem_u32(const void* p) {
    uint32_t a;
    asm("{ .reg .u64 t; cvta.to.shared.u64 t, %1; cvt.u32.u64 %0, t; }"
        : "=r"(a) : "l"(p));
    return a;
}
__device__ __forceinline__ void ldsm_x4(uint32_t* r, uint32_t addr) {
    asm volatile("ldmatrix.sync.aligned.m8n8.x4.shared.b16 {%0,%1,%2,%3}, [%4];"
                 : "=r"(r[0]), "=r"(r[1]), "=r"(r[2]), "=r"(r[3]) : "r"(addr));
}
__device__ __forceinline__ void mma_f16(float* c, const uint32_t* a,
                                        const uint32_t* b) {
    asm volatile(
        "mma.sync.aligned.m16n8k16.row.col.f32.f16.f16.f32 "
        "{%0,%1,%2,%3}, {%4,%5,%6,%7}, {%8,%9}, {%0,%1,%2,%3};"
        : "+f"(c[0]), "+f"(c[1]), "+f"(c[2]), "+f"(c[3])
        : "r"(a[0]), "r"(a[1]), "r"(a[2]), "r"(a[3]), "r"(b[0]), "r"(b[1]));
}
__device__ __forceinline__ void cp16(uint32_t dst, const void* src) {
    asm volatile("cp.async.cg.shared.global [%0], [%1], 16;"
                 :: "r"(dst), "l"(src) : "memory");
}
#define CP_COMMIT()  asm volatile("cp.async.commit_group;" ::: "memory")
#define CP_WAIT(n)   asm volatile("cp.async.wait_group %0;" :: "n"(n) : "memory")

__device__ __forceinline__ void split_f16(float x, uint16_t& h, uint16_t& l) {
    __half hb = __float2half_rn(x);
    float r = x - __half2float(hb);
    __half lb = __float2half_rn(r);
    h = __half_as_ushort(hb);
    l = __half_as_ushort(lb);
}
__device__ __forceinline__ void split_pack2(float x, float y,
                                            uint32_t& hp, uint32_t& lp) {
    uint16_t hx, lx, hy, ly;
    split_f16(x, hx, lx);
    split_f16(y, hy, ly);
    hp = (uint32_t)hx | ((uint32_t)hy << 16);
    lp = (uint32_t)lx | ((uint32_t)ly << 16);
}
__device__ __forceinline__ uint32_t pack_h2(float lo, float hi) {
    __half2 h = __floats2half2_rn(lo, hi);
    return *(uint32_t*)&h;
}

// ---------------------------------------------------------------------------
// Fused convert: 7 tensors fp32 -> (hi, lo) fp16 in one launch
// ---------------------------------------------------------------------------
struct CvtArgs {
    const float*    in[7];
    unsigned short* hi[7];
    unsigned short* lo[7];
};

__global__ void convert_all_kernel(CvtArgs args, int n4_act, int n4_w)
{
    const int z  = blockIdx.y;
    const int n4 = (z < 3) ? n4_act : n4_w;
    const float* in = args.in[z];
    unsigned short* hi = args.hi[z];
    unsigned short* lo = args.lo[z];
    const int stride = gridDim.x * blockDim.x;
    for (int i = blockIdx.x * blockDim.x + threadIdx.x; i < n4; i += stride) {
        float4 v = ((const float4*)in)[i];
        uint32_t h0, l0, h1, l1;
        split_pack2(v.x, v.y, h0, l0);
        split_pack2(v.z, v.w, h1, l1);
        ((uint2*)hi)[i] = make_uint2(h0, h1);
        ((uint2*)lo)[i] = make_uint2(l0, l1);
    }
}

// ---------------------------------------------------------------------------
// Mask -> bitmask (1 bit per entry)
// ---------------------------------------------------------------------------
__global__ void mask_bits_kernel(const int* __restrict__ mask)
{
    const int w = blockIdx.x * blockDim.x + threadIdx.x;
    if (w >= S_*S_/32) return;
    const int4* p = (const int4*)(mask + (size_t)w * 32);
    uint32_t bits = 0;
#pragma unroll
    for (int i = 0; i < 8; i++) {
        int4 v = p[i];
        bits |= (uint32_t)(v.x != 0) << (i*4 + 0);
        bits |= (uint32_t)(v.y != 0) << (i*4 + 1);
        bits |= (uint32_t)(v.z != 0) << (i*4 + 2);
        bits |= (uint32_t)(v.w != 0) << (i*4 + 3);
    }
    m_bits[w] = bits;
}

// ---------------------------------------------------------------------------
// GEMM core (fp16 split, 3-term), shared by QKV-fused and output kernels.
// CTA 128x128, BK=32, 8 warps, cp.async 2-stage.
// MODE 0: fp16 h/l head layout [bh][s][dk]
// MODE 1: fp16 h (+skip lo) transposed head layout [bh][dk][s]
// MODE 2: fp32 natural [m][n]
// ---------------------------------------------------------------------------
#define GROWB  80
#define GARR   (128 * GROWB)
#define GSTAGE (4 * GARR)
#define GSMEM  (2 * GSTAGE)              // 81920 B

__device__ __forceinline__ void gemm_core(
    const unsigned short* __restrict__ Ah,
    const unsigned short* __restrict__ Al,
    const unsigned short* __restrict__ Wh,
    const unsigned short* __restrict__ Wl,
    const float* __restrict__ bias,
    float* __restrict__ out32,
    unsigned short* __restrict__ outh,
    unsigned short* __restrict__ outl,
    int mode, int bm, int bn)
{
    extern __shared__ char dsm[];
    const uint32_t sbase = smem_u32(dsm);

    const int tid  = threadIdx.x;
    const int lane = tid & 31;
    const int warp = tid >> 5;
    const int wm   = warp >> 2;
    const int wn   = warp & 3;

    const int arow = (lane & 7) + ((lane >> 3) & 1) * 8;
    const int acol = ((lane >> 4) & 1) * 8;
    const int brow = (lane & 7) + ((lane >> 4) & 1) * 8;
    const int bcol = ((lane >> 3) & 1) * 8;

    const int r    = tid >> 1;
    const int half = tid & 1;
    const unsigned short* Ap  = Ah + (size_t)(bm * 128 + r) * D_ + half * 16;
    const unsigned short* Alp = Al + (size_t)(bm * 128 + r) * D_ + half * 16;
    const unsigned short* Wp  = Wh + (size_t)(bn * 128 + r) * D_ + half * 16;
    const unsigned short* Wlp = Wl + (size_t)(bn * 128 + r) * D_ + half * 16;
    const uint32_t st_off = (uint32_t)(r * GROWB + half * 32);

    float acc[4][4][4];
#pragma unroll
    for (int i = 0; i < 4; i++)
#pragma unroll
        for (int j = 0; j < 4; j++)
#pragma unroll
            for (int e = 0; e < 4; e++) acc[i][j][e] = 0.f;

    auto load_chunk = [&](int c, uint32_t stg) {
        const int kt = c * 32;
        const uint32_t a0 = stg + st_off;
        cp16(a0,              Ap + kt);
        cp16(a0 + 16,         Ap + kt + 8);
        cp16(a0 + GARR,       Alp + kt);
        cp16(a0 + GARR + 16,  Alp + kt + 8);
        cp16(a0 + 2*GARR,      Wp + kt);
        cp16(a0 + 2*GARR + 16, Wp + kt + 8);
        cp16(a0 + 3*GARR,      Wlp + kt);
        cp16(a0 + 3*GARR + 16, Wlp + kt + 8);
    };

    load_chunk(0, sbase);
    CP_COMMIT();

    const uint32_t aoff0 = (uint32_t)((wm * 64 + arow) * GROWB + acol * 2);
    const uint32_t boff0 = (uint32_t)((wn * 32 + brow) * GROWB + bcol * 2);

    for (int c = 0; c < 32; c++) {
        const uint32_t stg = sbase + (uint32_t)(c & 1) * GSTAGE;
        if (c < 31) {
            load_chunk(c + 1, sbase + (uint32_t)((c + 1) & 1) * GSTAGE);
            CP_COMMIT();
            CP_WAIT(1);
        } else {
            CP_WAIT(0);
        }
        __syncthreads();

#pragma unroll
        for (int ks = 0; ks < 2; ks++) {
            const uint32_t kb = (uint32_t)(ks * 32);
            uint32_t aH[4][4], aL[4][4];
#pragma unroll
            for (int mt = 0; mt < 4; mt++) {
                const uint32_t ao = stg + aoff0 + (uint32_t)(mt*16*GROWB) + kb;
                ldsm_x4(aH[mt], ao);
                ldsm_x4(aL[mt], ao + GARR);
            }
            uint32_t bH[2][4], bL[2][4];
#pragma unroll
            for (int ng = 0; ng < 2; ng++) {
                const uint32_t bo = stg + 2*GARR + boff0
                                  + (uint32_t)(ng*16*GROWB) + kb;
                ldsm_x4(bH[ng], bo);
                ldsm_x4(bL[ng], bo + GARR);
            }
#pragma unroll
            for (int mt = 0; mt < 4; mt++) {
#pragma unroll
                for (int nt = 0; nt < 4; nt++) {
                    const uint32_t* bh = &bH[nt >> 1][(nt & 1) * 2];
                    const uint32_t* bl = &bL[nt >> 1][(nt & 1) * 2];
                    mma_f16(acc[mt][nt], aH[mt], bh);
                    mma_f16(acc[mt][nt], aH[mt], bl);
                    mma_f16(acc[mt][nt], aL[mt], bh);
                }
            }
        }
        __syncthreads();
    }

    // Epilogue
    const int rl = lane >> 2;
    const int cl = 2 * (lane & 3);
#pragma unroll
    for (int mt = 0; mt < 4; mt++) {
#pragma unroll
        for (int nt = 0; nt < 4; nt++) {
            const int n = bn * 128 + wn * 32 + nt * 8 + cl;
            const float b0 = bias[n], b1 = bias[n + 1];
#pragma unroll
            for (int hf = 0; hf < 2; hf++) {
                const int m = bm * 128 + wm * 64 + mt * 16 + rl + hf * 8;
                const float vx = acc[mt][nt][hf * 2 + 0] + b0;
                const float vy = acc[mt][nt][hf * 2 + 1] + b1;
                const int h  = n >> 6;
                const int dk = n & 63;
                const int bb = m >> 11;
                const int ss = m & 2047;
                if (mode == 2) {
                    *(float2*)(out32 + (size_t)m * D_ + n) = make_float2(vx, vy);
                } else if (mode == 0) {
                    const size_t idx = ((size_t)((bb*H_ + h)*S_ + ss))*DK_ + dk;
                    uint32_t hp, lp;
                    split_pack2(vx, vy, hp, lp);
                    *(uint32_t*)(outh + idx) = hp;
                    *(uint32_t*)(outl + idx) = lp;
                } else {
                    // transposed, hi digit only (flash uses single-digit V)
                    const size_t idx = ((size_t)((bb*H_ + h)*DK_ + dk))*S_ + ss;
                    outh[idx]      = __half_as_ushort(__float2half_rn(vx));
                    outh[idx + S_] = __half_as_ushort(__float2half_rn(vy));
                }
            }
        }
    }
}

struct QKVArgs {
    const unsigned short* Ah[3];
    const unsigned short* Al[3];
    const unsigned short* Wh[3];
    const unsigned short* Wl[3];
    const float*          bias[3];
    unsigned short*       outh[3];
    unsigned short*       outl[3];
};

__global__ __launch_bounds__(256)
void gemm_qkv_kernel(QKVArgs a)
{
    const int z = blockIdx.z;
    gemm_core(a.Ah[z], a.Al[z], a.Wh[z], a.Wl[z], a.bias[z],
              nullptr, a.outh[z], a.outl[z],
              (z == 2) ? 1 : 0, blockIdx.y, blockIdx.x);
}

__global__ __launch_bounds__(256)
void gemm_out_kernel(const unsigned short* Ah, const unsigned short* Al,
                     const unsigned short* Wh, const unsigned short* Wl,
                     const float* bias, float* out32)
{
    gemm_core(Ah, Al, Wh, Wl, bias, out32, nullptr, nullptr,
              2, blockIdx.y, blockIdx.x);
}

// ---------------------------------------------------------------------------
// Tensor-core flash attention: Q 2-digit, K 1-digit, V 1-digit.
// S = (Qh+Ql)·Kh (2 MMAs), PV = P·Vh (1 MMA). 2 CTAs/SM.
// ---------------------------------------------------------------------------
#define QKROWB 144
#define VTROWB 272
#define QK_BYTES (128 * QKROWB)          // 18432
#define VT_BYTES (64 * VTROWB)           // 17408
#define FQ_H  0
#define FQ_L  QK_BYTES
#define FSTG0 (2 * QK_BYTES)             // 36864
#define SG_KH 0
#define SG_VH QK_BYTES
#define STG_B (QK_BYTES + VT_BYTES)      // 35840
#define F_SMEM (FSTG0 + 2 * STG_B)       // 108544

__global__ __launch_bounds__(256, 2)
void flash_mma_kernel()
{
    extern __shared__ char dsm[];
    const uint32_t sb = smem_u32(dsm);

    const int tid  = threadIdx.x;
    const int lane = tid & 31;
    const int warp = tid >> 5;
    const int qb   = blockIdx.x;
    const int bh   = blockIdx.y;
    const int q0   = qb * 128;

    const int arow = (lane & 7) + ((lane >> 3) & 1) * 8;
    const int acol = ((lane >> 4) & 1) * 8;
    const int brow = (lane & 7) + ((lane >> 4) & 1) * 8;
    const int bcol = ((lane >> 3) & 1) * 8;
    const int ln2  = lane & 3;
    const int r0   = warp * 16 + (lane >> 2);

    const unsigned short* Qhp = p_qh + (size_t)bh * S_ * DK_;
    const unsigned short* Qlp = p_ql + (size_t)bh * S_ * DK_;
    const unsigned short* Khp = p_kh + (size_t)bh * S_ * DK_;
    const unsigned short* Vhp = p_vth + (size_t)bh * DK_ * S_;

    const int row  = tid >> 1, seg  = tid & 1;
    const int vrow = tid >> 2, vseg = tid & 3;

    auto load_kv = [&](int t0, int buf) {
        const uint32_t st = sb + FSTG0 + (uint32_t)buf * STG_B;
        const size_t g = (size_t)(t0 + row) * DK_ + seg * 32;
        const uint32_t s = st + row * QKROWB + seg * 64;
#pragma unroll
        for (int i = 0; i < 4; i++)
            cp16(s + SG_KH + i*16, Khp + g + i*8);
        const size_t gv = (size_t)vrow * S_ + t0 + vseg * 32;
        const uint32_t sv = st + vrow * VTROWB + vseg * 64;
#pragma unroll
        for (int i = 0; i < 4; i++)
            cp16(sv + SG_VH + i*16, Vhp + gv + i*8);
    };

    {
        const size_t g = (size_t)(q0 + row) * DK_ + seg * 32;
        const uint32_t s = sb + row * QKROWB + seg * 64;
#pragma unroll
        for (int i = 0; i < 4; i++) {
            cp16(s + FQ_H + i*16, Qhp + g + i*8);
            cp16(s + FQ_L + i*16, Qlp + g + i*8);
        }
    }
    load_kv(0, 0);
    CP_COMMIT();

    float m0 = -1e30f, m1 = -1e30f, l0 = 0.f, l1 = 0.f;
    float oacc[8][4];
#pragma unroll
    for (int j = 0; j < 8; j++)
#pragma unroll
        for (int e = 0; e < 4; e++) oacc[j][e] = 0.f;

    for (int it = 0; it < 16; it++) {
        const int buf = it & 1;
        if (it < 15) {
            load_kv((it + 1) * 128, 1 - buf);
            CP_COMMIT();
            CP_WAIT(1);
        } else {
            CP_WAIT(0);
        }
        __syncthreads();
        const uint32_t st = sb + FSTG0 + (uint32_t)buf * STG_B;

        // ---- S = Q K^T (Q 2-digit, K 1-digit)
        float sacc[16][4];
#pragma unroll
        for (int j = 0; j < 16; j++)
#pragma unroll
            for (int e = 0; e < 4; e++) sacc[j][e] = 0.f;

#pragma unroll
        for (int ks = 0; ks < 4; ks++) {
            const uint32_t kb = (uint32_t)(ks * 32);
            uint32_t aH[4], aL[4];
            const uint32_t ao = sb + (warp*16 + arow) * QKROWB + acol*2 + kb;
            ldsm_x4(aH, ao + FQ_H);
            ldsm_x4(aL, ao + FQ_L);
#pragma unroll
            for (int j16 = 0; j16 < 8; j16++) {
                uint32_t bH[4];
                const uint32_t bo = st + (j16*16 + brow) * QKROWB + bcol*2 + kb;
                ldsm_x4(bH, bo + SG_KH);
#pragma unroll
                for (int hf = 0; hf < 2; hf++) {
                    float* a2 = sacc[j16*2 + hf];
                    mma_f16(a2, aH, &bH[hf*2]);
                    mma_f16(a2, aL, &bH[hf*2]);
                }
            }
        }

        // ---- mask (bitmask) + online softmax; P stays in registers
#pragma unroll
        for (int p = 0; p < 2; p++) {
            const int r  = r0 + p * 8;
            const int eb = p * 2;
            const uint4 mw = ((const uint4*)m_bits)[(size_t)(q0 + r) * 16 + it];
            const bool allset =
                (mw.x & mw.y & mw.z & mw.w) == 0xffffffffu;

            float mx = -1e30f;
            if (allset) {
#pragma unroll
                for (int j = 0; j < 16; j++) {
                    const float v0 = sacc[j][eb+0] * 0.125f;
                    const float v1 = sacc[j][eb+1] * 0.125f;
                    sacc[j][eb+0] = v0;
                    sacc[j][eb+1] = v1;
                    mx = fmaxf(mx, fmaxf(v0, v1));
                }
            } else {
                const uint32_t ws[4] = {mw.x, mw.y, mw.z, mw.w};
#pragma unroll
                for (int j = 0; j < 16; j++) {
                    const uint32_t wj = ws[j >> 2];
                    const int bit0 = (j & 3) * 8 + 2 * ln2;
                    float v0 = sacc[j][eb+0] * 0.125f;
                    float v1 = sacc[j][eb+1] * 0.125f;
                    if (!((wj >> bit0) & 1u))       v0 = -1e9f;
                    if (!((wj >> (bit0 + 1)) & 1u)) v1 = -1e9f;
                    sacc[j][eb+0] = v0;
                    sacc[j][eb+1] = v1;
                    mx = fmaxf(mx, fmaxf(v0, v1));
                }
            }
            mx = fmaxf(mx, __shfl_xor_sync(0xffffffffu, mx, 1));
            mx = fmaxf(mx, __shfl_xor_sync(0xffffffffu, mx, 2));

            const float mp   = (p == 0) ? m0 : m1;
            const float mnew = fmaxf(mp, mx);
            const float corr = __expf(mp - mnew);
            float sum = 0.f;
#pragma unroll
            for (int j = 0; j < 16; j++) {
                const float p0 = __expf(sacc[j][eb+0] - mnew);
                const float p1 = __expf(sacc[j][eb+1] - mnew);
                sacc[j][eb+0] = p0;
                sacc[j][eb+1] = p1;
                sum += p0 + p1;
            }
            sum += __shfl_xor_sync(0xffffffffu, sum, 1);
            sum += __shfl_xor_sync(0xffffffffu, sum, 2);

            if (p == 0) { l0 = l0 * corr + sum; m0 = mnew; }
            else        { l1 = l1 * corr + sum; m1 = mnew; }
#pragma unroll
            for (int j = 0; j < 8; j++) {
                oacc[j][eb+0] *= corr;
                oacc[j][eb+1] *= corr;
            }
        }

        // ---- O += P V (V 1-digit)
#pragma unroll
        for (int ks = 0; ks < 8; ks++) {
            uint32_t aP[4];
            aP[0] = pack_h2(sacc[2*ks  ][0], sacc[2*ks  ][1]);
            aP[1] = pack_h2(sacc[2*ks  ][2], sacc[2*ks  ][3]);
            aP[2] = pack_h2(sacc[2*ks+1][0], sacc[2*ks+1][1]);
            aP[3] = pack_h2(sacc[2*ks+1][2], sacc[2*ks+1][3]);
            const uint32_t kb = (uint32_t)(ks * 32);
#pragma unroll
            for (int j16 = 0; j16 < 4; j16++) {
                uint32_t bH[4];
                const uint32_t bo = st + (j16*16 + brow) * VTROWB + bcol*2 + kb;
                ldsm_x4(bH, bo + SG_VH);
                mma_f16(oacc[j16*2 + 0], aP, &bH[0]);
                mma_f16(oacc[j16*2 + 1], aP, &bH[2]);
            }
        }
        __syncthreads();
    }

    // ---- epilogue: X[b][s][h*64+dk] fp16 hi/lo
    const int bb = bh >> 4, hh = bh & 15;
#pragma unroll
    for (int p = 0; p < 2; p++) {
        const int r   = r0 + p * 8;
        const int eb  = p * 2;
        const float inv = 1.f / ((p == 0) ? l0 : l1);
        const size_t base = ((size_t)(bb * S_ + q0 + r)) * D_ + hh * DK_ + 2*ln2;
#pragma unroll
        for (int j = 0; j < 8; j++) {
            uint32_t hp, lp;
            split_pack2(oacc[j][eb+0] * inv, oacc[j][eb+1] * inv, hp, lp);
            *(uint32_t*)(x_h + base + j*8) = hp;
            *(uint32_t*)(x_l + base + j*8) = lp;
        }
    }
}

// ---------------------------------------------------------------------------
extern "C" void kernel_launch(void* const* d_in, const int* in_sizes, int n_in,
                              void* d_out, int out_size)
{
    (void)in_sizes; (void)n_in; (void)out_size;
    const float* query = (const float*)d_in[0];
    const float* key_  = (const float*)d_in[1];
    const float* value = (const float*)d_in[2];
    const int*   mask  = (const int*)  d_in[3];
    const float* Wq    = (const float*)d_in[4];
    const float* bq    = (const float*)d_in[5];
    const float* Wk    = (const float*)d_in[6];
    const float* bk    = (const float*)d_in[7];
    const float* Wv    = (const float*)d_in[8];
    const float* bv    = (const float*)d_in[9];
    const float* Wo    = (const float*)d_in[10];
    const float* bo    = (const float*)d_in[11];
    float* out = (float*)d_out;

    cudaFuncSetAttribute(flash_mma_kernel,
                         cudaFuncAttributeMaxDynamicSharedMemorySize, F_SMEM);
    cudaFuncSetAttribute(gemm_qkv_kernel,
                         cudaFuncAttributeMaxDynamicSharedMemorySize, GSMEM);
    cudaFuncSetAttribute(gemm_out_kernel,
                         cudaFuncAttributeMaxDynamicSharedMemorySize, GSMEM);

    void *cqh,*cql,*ckh,*ckl,*cvh,*cvl;
    void *wqh,*wql,*wkh,*wkl,*wvh,*wvl,*woh,*wol;
    void *pqh,*pql,*pkh,*pkl,*pvth,*pvtl,*xh,*xl;
    cudaGetSymbolAddress(&cqh, c_qh); cudaGetSymbolAddress(&cql, c_ql);
    cudaGetSymbolAddress(&ckh, c_kh); cudaGetSymbolAddress(&ckl, c_kl);
    cudaGetSymbolAddress(&cvh, c_vh); cudaGetSymbolAddress(&cvl, c_vl);
    cudaGetSymbolAddress(&wqh, w_qh); cudaGetSymbolAddress(&wql, w_ql);
    cudaGetSymbolAddress(&wkh, w_kh); cudaGetSymbolAddress(&wkl, w_kl);
    cudaGetSymbolAddress(&wvh, w_vh); cudaGetSymbolAddress(&wvl, w_vl);
    cudaGetSymbolAddress(&woh, w_oh); cudaGetSymbolAddress(&wol, w_ol);
    cudaGetSymbolAddress(&pqh, p_qh); cudaGetSymbolAddress(&pql, p_ql);
    cudaGetSymbolAddress(&pkh, p_kh); cudaGetSymbolAddress(&pkl, p_kl);
    cudaGetSymbolAddress(&pvth, p_vth); cudaGetSymbolAddress(&pvtl, p_vtl);
    cudaGetSymbolAddress(&xh, x_h); cudaGetSymbolAddress(&xl, x_l);

    typedef unsigned short us;

    // 1) fused convert
    CvtArgs ca;
    ca.in[0] = query; ca.hi[0] = (us*)cqh; ca.lo[0] = (us*)cql;
    ca.in[1] = key_;  ca.hi[1] = (us*)ckh; ca.lo[1] = (us*)ckl;
    ca.in[2] = value; ca.hi[2] = (us*)cvh; ca.lo[2] = (us*)cvl;
    ca.in[3] = Wq;    ca.hi[3] = (us*)wqh; ca.lo[3] = (us*)wql;
    ca.in[4] = Wk;    ca.hi[4] = (us*)wkh; ca.lo[4] = (us*)wkl;
    ca.in[5] = Wv;    ca.hi[5] = (us*)wvh; ca.lo[5] = (us*)wvl;
    ca.in[6] = Wo;    ca.hi[6] = (us*)woh; ca.lo[6] = (us*)wol;
    convert_all_kernel<<<dim3(512, 7), 256>>>(ca, M_*D_/4, D_*D_/4);

    // 2) mask bitmask
    mask_bits_kernel<<<S_*S_/32/256, 256>>>(mask);

    // 3) fused Q/K/V projections (one launch, z = 3)
    QKVArgs qa;
    qa.Ah[0] = (const us*)cqh; qa.Al[0] = (const us*)cql;
    qa.Wh[0] = (const us*)wqh; qa.Wl[0] = (const us*)wql;
    qa.bias[0] = bq; qa.outh[0] = (us*)pqh; qa.outl[0] = (us*)pql;
    qa.Ah[1] = (const us*)ckh; qa.Al[1] = (const us*)ckl;
    qa.Wh[1] = (const us*)wkh; qa.Wl[1] = (const us*)wkl;
    qa.bias[1] = bk; qa.outh[1] = (us*)pkh; qa.outl[1] = (us*)pkl;
    qa.Ah[2] = (const us*)cvh; qa.Al[2] = (const us*)cvl;
    qa.Wh[2] = (const us*)wvh; qa.Wl[2] = (const us*)wvl;
    qa.bias[2] = bv; qa.outh[2] = (us*)pvth; qa.outl[2] = (us*)pvtl;
    gemm_qkv_kernel<<<dim3(D_/128, M_/128, 3), 256, GSMEM>>>(qa);

    // 4) flash attention (2 CTAs/SM)
    flash_mma_kernel<<<dim3(S_/128, B_*H_), 256, F_SMEM>>>();

    // 5) output projection
    gemm_out_kernel<<<dim3(D_/128, M_/128), 256, GSMEM>>>(
        (const us*)xh, (const us*)xl, (const us*)woh, (const us*)wol,
        bo, out);
}

// round 15
// speedup vs baseline: 1.0018x; 1.0018x over previous
#include <cuda_runtime.h>
#include <cuda_fp16.h>
#include <cstdint>

#define B_  4
#define S_  2048
#define D_  1024
#define H_  16
#define DK_ 64
#define M_  (B_*S_)

// ---------------------------------------------------------------------------
// Scratch (fp16 bit-patterns in ushort arrays; no allocation APIs)
// ---------------------------------------------------------------------------
__device__ unsigned short c_qh[M_*D_], c_ql[M_*D_];
__device__ unsigned short c_kh[M_*D_], c_kl[M_*D_];
__device__ unsigned short c_vh[M_*D_], c_vl[M_*D_];
__device__ unsigned short w_qh[D_*D_], w_ql[D_*D_];
__device__ unsigned short w_kh[D_*D_], w_kl[D_*D_];
__device__ unsigned short w_vh[D_*D_], w_vl[D_*D_];
__device__ unsigned short w_oh[D_*D_], w_ol[D_*D_];
__device__ unsigned short p_qh[M_*D_], p_ql[M_*D_];   // Q proj, [bh][s][dk]
__device__ unsigned short p_kh[M_*D_], p_kl[M_*D_];   // K proj, [bh][s][dk]
__device__ unsigned short p_vth[M_*D_], p_vtl[M_*D_]; // V proj, [bh][dk][s]
__device__ unsigned short x_h[M_*D_], x_l[M_*D_];     // attn out, [b][s][d]
__device__ unsigned int   m_bits[S_*S_/32];           // mask bitmask

// ---------------------------------------------------------------------------
// Helpers
// ---------------------------------------------------------------------------
__device__ __forceinline__ uint32_t smem_u32(const void* p) {
    uint32_t a;
    asm("{ .reg .u64 t; cvta.to.shared.u64 t, %1; cvt.u32.u64 %0, t; }"
        : "=r"(a) : "l"(p));
    return a;
}
__device__ __forceinline__ void ldsm_x4(uint32_t* r, uint32_t addr) {
    asm volatile("ldmatrix.sync.aligned.m8n8.x4.shared.b16 {%0,%1,%2,%3}, [%4];"
                 : "=r"(r[0]), "=r"(r[1]), "=r"(r[2]), "=r"(r[3]) : "r"(addr));
}
__device__ __forceinline__ void mma_f16(float* c, const uint32_t* a,
                                        const uint32_t* b) {
    asm volatile(
        "mma.sync.aligned.m16n8k16.row.col.f32.f16.f16.f32 "
        "{%0,%1,%2,%3}, {%4,%5,%6,%7}, {%8,%9}, {%0,%1,%2,%3};"
        : "+f"(c[0]), "+f"(c[1]), "+f"(c[2]), "+f"(c[3])
        : "r"(a[0]), "r"(a[1]), "r"(a[2]), "r"(a[3]), "r"(b[0]), "r"(b[1]));
}
__device__ __forceinline__ void cp16(uint32_t dst, const void* src) {
    asm volatile("cp.async.cg.shared.global [%0], [%1], 16;"
                 :: "r"(dst), "l"(src) : "memory");
}
#define CP_COMMIT()  asm volatile("cp.async.commit_group;" ::: "memory")
#define CP_WAIT(n)   asm volatile("cp.async.wait_group %0;" :: "n"(n) : "memory")

__device__ __forceinline__ void split_f16(float x, uint16_t& h, uint16_t& l) {
    __half hb = __float2half_rn(x);
    float r = x - __half2float(hb);
    __half lb = __float2half_rn(r);
    h = __half_as_ushort(hb);
    l = __half_as_ushort(lb);
}
__device__ __forceinline__ void split_pack2(float x, float y,
                                            uint32_t& hp, uint32_t& lp) {
    uint16_t hx, lx, hy, ly;
    split_f16(x, hx, lx);
    split_f16(y, hy, ly);
    hp = (uint32_t)hx | ((uint32_t)hy << 16);
    lp = (uint32_t)lx | ((uint32_t)ly << 16);
}
__device__ __forceinline__ uint32_t pack_h2(float lo, float hi) {
    __half2 h = __floats2half2_rn(lo, hi);
    return *(uint32_t*)&h;
}

// ---------------------------------------------------------------------------
// Fused convert: 7 tensors fp32 -> (hi, lo) fp16 in one launch
// ---------------------------------------------------------------------------
struct CvtArgs {
    const float*    in[7];
    unsigned short* hi[7];
    unsigned short* lo[7];
};

__global__ void convert_all_kernel(CvtArgs args, int n4_act, int n4_w)
{
    const int z  = blockIdx.y;
    const int n4 = (z < 3) ? n4_act : n4_w;
    const float* in = args.in[z];
    unsigned short* hi = args.hi[z];
    unsigned short* lo = args.lo[z];
    const int stride = gridDim.x * blockDim.x;
    for (int i = blockIdx.x * blockDim.x + threadIdx.x; i < n4; i += stride) {
        float4 v = ((const float4*)in)[i];
        uint32_t h0, l0, h1, l1;
        split_pack2(v.x, v.y, h0, l0);
        split_pack2(v.z, v.w, h1, l1);
        ((uint2*)hi)[i] = make_uint2(h0, h1);
        ((uint2*)lo)[i] = make_uint2(l0, l1);
    }
}

// ---------------------------------------------------------------------------
// Mask -> bitmask (1 bit per entry)
// ---------------------------------------------------------------------------
__global__ void mask_bits_kernel(const int* __restrict__ mask)
{
    const int w = blockIdx.x * blockDim.x + threadIdx.x;
    if (w >= S_*S_/32) return;
    const int4* p = (const int4*)(mask + (size_t)w * 32);
    uint32_t bits = 0;
#pragma unroll
    for (int i = 0; i < 8; i++) {
        int4 v = p[i];
        bits |= (uint32_t)(v.x != 0) << (i*4 + 0);
        bits |= (uint32_t)(v.y != 0) << (i*4 + 1);
        bits |= (uint32_t)(v.z != 0) << (i*4 + 2);
        bits |= (uint32_t)(v.w != 0) << (i*4 + 3);
    }
    m_bits[w] = bits;
}

// ---------------------------------------------------------------------------
// GEMM core (fp16 split, 3-term), shared by QKV-fused and output kernels.
// CTA 128x128, BK=32, 8 warps, cp.async 2-stage.
// MODE 0: fp16 h/l head layout [bh][s][dk]
// MODE 1: fp16 h (+skip lo) transposed head layout [bh][dk][s]
// MODE 2: fp32 natural [m][n]
// ---------------------------------------------------------------------------
#define GROWB  80
#define GARR   (128 * GROWB)
#define GSTAGE (4 * GARR)
#define GSMEM  (2 * GSTAGE)              // 81920 B

__device__ __forceinline__ void gemm_core(
    const unsigned short* __restrict__ Ah,
    const unsigned short* __restrict__ Al,
    const unsigned short* __restrict__ Wh,
    const unsigned short* __restrict__ Wl,
    const float* __restrict__ bias,
    float* __restrict__ out32,
    unsigned short* __restrict__ outh,
    unsigned short* __restrict__ outl,
    int mode, int bm, int bn)
{
    extern __shared__ char dsm[];
    const uint32_t sbase = smem_u32(dsm);

    const int tid  = threadIdx.x;
    const int lane = tid & 31;
    const int warp = tid >> 5;
    const int wm   = warp >> 2;
    const int wn   = warp & 3;

    const int arow = (lane & 7) + ((lane >> 3) & 1) * 8;
    const int acol = ((lane >> 4) & 1) * 8;
    const int brow = (lane & 7) + ((lane >> 4) & 1) * 8;
    const int bcol = ((lane >> 3) & 1) * 8;

    const int r    = tid >> 1;
    const int half = tid & 1;
    const unsigned short* Ap  = Ah + (size_t)(bm * 128 + r) * D_ + half * 16;
    const unsigned short* Alp = Al + (size_t)(bm * 128 + r) * D_ + half * 16;
    const unsigned short* Wp  = Wh + (size_t)(bn * 128 + r) * D_ + half * 16;
    const unsigned short* Wlp = Wl + (size_t)(bn * 128 + r) * D_ + half * 16;
    const uint32_t st_off = (uint32_t)(r * GROWB + half * 32);

    float acc[4][4][4];
#pragma unroll
    for (int i = 0; i < 4; i++)
#pragma unroll
        for (int j = 0; j < 4; j++)
#pragma unroll
            for (int e = 0; e < 4; e++) acc[i][j][e] = 0.f;

    auto load_chunk = [&](int c, uint32_t stg) {
        const int kt = c * 32;
        const uint32_t a0 = stg + st_off;
        cp16(a0,              Ap + kt);
        cp16(a0 + 16,         Ap + kt + 8);
        cp16(a0 + GARR,       Alp + kt);
        cp16(a0 + GARR + 16,  Alp + kt + 8);
        cp16(a0 + 2*GARR,      Wp + kt);
        cp16(a0 + 2*GARR + 16, Wp + kt + 8);
        cp16(a0 + 3*GARR,      Wlp + kt);
        cp16(a0 + 3*GARR + 16, Wlp + kt + 8);
    };

    load_chunk(0, sbase);
    CP_COMMIT();

    const uint32_t aoff0 = (uint32_t)((wm * 64 + arow) * GROWB + acol * 2);
    const uint32_t boff0 = (uint32_t)((wn * 32 + brow) * GROWB + bcol * 2);

    for (int c = 0; c < 32; c++) {
        const uint32_t stg = sbase + (uint32_t)(c & 1) * GSTAGE;
        if (c < 31) {
            load_chunk(c + 1, sbase + (uint32_t)((c + 1) & 1) * GSTAGE);
            CP_COMMIT();
            CP_WAIT(1);
        } else {
            CP_WAIT(0);
        }
        __syncthreads();

#pragma unroll
        for (int ks = 0; ks < 2; ks++) {
            const uint32_t kb = (uint32_t)(ks * 32);
            uint32_t aH[4][4], aL[4][4];
#pragma unroll
            for (int mt = 0; mt < 4; mt++) {
                const uint32_t ao = stg + aoff0 + (uint32_t)(mt*16*GROWB) + kb;
                ldsm_x4(aH[mt], ao);
                ldsm_x4(aL[mt], ao + GARR);
            }
            uint32_t bH[2][4], bL[2][4];
#pragma unroll
            for (int ng = 0; ng < 2; ng++) {
                const uint32_t bo = stg + 2*GARR + boff0
                                  + (uint32_t)(ng*16*GROWB) + kb;
                ldsm_x4(bH[ng], bo);
                ldsm_x4(bL[ng], bo + GARR);
            }
#pragma unroll
            for (int mt = 0; mt < 4; mt++) {
#pragma unroll
                for (int nt = 0; nt < 4; nt++) {
                    const uint32_t* bh = &bH[nt >> 1][(nt & 1) * 2];
                    const uint32_t* bl = &bL[nt >> 1][(nt & 1) * 2];
                    mma_f16(acc[mt][nt], aH[mt], bh);
                    mma_f16(acc[mt][nt], aH[mt], bl);
                    mma_f16(acc[mt][nt], aL[mt], bh);
                }
            }
        }
        __syncthreads();
    }

    // Epilogue
    const int rl = lane >> 2;
    const int cl = 2 * (lane & 3);
#pragma unroll
    for (int mt = 0; mt < 4; mt++) {
#pragma unroll
        for (int nt = 0; nt < 4; nt++) {
            const int n = bn * 128 + wn * 32 + nt * 8 + cl;
            const float b0 = bias[n], b1 = bias[n + 1];
#pragma unroll
            for (int hf = 0; hf < 2; hf++) {
                const int m = bm * 128 + wm * 64 + mt * 16 + rl + hf * 8;
                const float vx = acc[mt][nt][hf * 2 + 0] + b0;
                const float vy = acc[mt][nt][hf * 2 + 1] + b1;
                const int h  = n >> 6;
                const int dk = n & 63;
                const int bb = m >> 11;
                const int ss = m & 2047;
                if (mode == 2) {
                    *(float2*)(out32 + (size_t)m * D_ + n) = make_float2(vx, vy);
                } else if (mode == 0) {
                    const size_t idx = ((size_t)((bb*H_ + h)*S_ + ss))*DK_ + dk;
                    uint32_t hp, lp;
                    split_pack2(vx, vy, hp, lp);
                    *(uint32_t*)(outh + idx) = hp;
                    *(uint32_t*)(outl + idx) = lp;
                } else {
                    // transposed, hi digit only (flash uses single-digit V)
                    const size_t idx = ((size_t)((bb*H_ + h)*DK_ + dk))*S_ + ss;
                    outh[idx]      = __half_as_ushort(__float2half_rn(vx));
                    outh[idx + S_] = __half_as_ushort(__float2half_rn(vy));
                }
            }
        }
    }
}

struct QKVArgs {
    const unsigned short* Ah[3];
    const unsigned short* Al[3];
    const unsigned short* Wh[3];
    const unsigned short* Wl[3];
    const float*          bias[3];
    unsigned short*       outh[3];
    unsigned short*       outl[3];
};

__global__ __launch_bounds__(256)
void gemm_qkv_kernel(QKVArgs a)
{
    const int z = blockIdx.z;
    gemm_core(a.Ah[z], a.Al[z], a.Wh[z], a.Wl[z], a.bias[z],
              nullptr, a.outh[z], a.outl[z],
              (z == 2) ? 1 : 0, blockIdx.y, blockIdx.x);
}

__global__ __launch_bounds__(256)
void gemm_out_kernel(const unsigned short* Ah, const unsigned short* Al,
                     const unsigned short* Wh, const unsigned short* Wl,
                     const float* bias, float* out32)
{
    gemm_core(Ah, Al, Wh, Wl, bias, out32, nullptr, nullptr,
              2, blockIdx.y, blockIdx.x);
}

// ---------------------------------------------------------------------------
// Tensor-core flash attention: Q 2-digit, K 1-digit, V 1-digit.
// S = (Qh+Ql)·Kh (2 MMAs), PV = P·Vh (1 MMA). 2 CTAs/SM.
// ---------------------------------------------------------------------------
#define QKROWB 144
#define VTROWB 272
#define QK_BYTES (128 * QKROWB)          // 18432
#define VT_BYTES (64 * VTROWB)           // 17408
#define FQ_H  0
#define FQ_L  QK_BYTES
#define FSTG0 (2 * QK_BYTES)             // 36864
#define SG_KH 0
#define SG_VH QK_BYTES
#define STG_B (QK_BYTES + VT_BYTES)      // 35840
#define F_SMEM (FSTG0 + 2 * STG_B)       // 108544

__global__ __launch_bounds__(256, 2)
void flash_mma_kernel()
{
    extern __shared__ char dsm[];
    const uint32_t sb = smem_u32(dsm);

    const int tid  = threadIdx.x;
    const int lane = tid & 31;
    const int warp = tid >> 5;
    const int qb   = blockIdx.x;
    const int bh   = blockIdx.y;
    const int q0   = qb * 128;

    const int arow = (lane & 7) + ((lane >> 3) & 1) * 8;
    const int acol = ((lane >> 4) & 1) * 8;
    const int brow = (lane & 7) + ((lane >> 4) & 1) * 8;
    const int bcol = ((lane >> 3) & 1) * 8;
    const int ln2  = lane & 3;
    const int r0   = warp * 16 + (lane >> 2);

    const unsigned short* Qhp = p_qh + (size_t)bh * S_ * DK_;
    const unsigned short* Qlp = p_ql + (size_t)bh * S_ * DK_;
    const unsigned short* Khp = p_kh + (size_t)bh * S_ * DK_;
    const unsigned short* Vhp = p_vth + (size_t)bh * DK_ * S_;

    const int row  = tid >> 1, seg  = tid & 1;
    const int vrow = tid >> 2, vseg = tid & 3;

    auto load_kv = [&](int t0, int buf) {
        const uint32_t st = sb + FSTG0 + (uint32_t)buf * STG_B;
        const size_t g = (size_t)(t0 + row) * DK_ + seg * 32;
        const uint32_t s = st + row * QKROWB + seg * 64;
#pragma unroll
        for (int i = 0; i < 4; i++)
            cp16(s + SG_KH + i*16, Khp + g + i*8);
        const size_t gv = (size_t)vrow * S_ + t0 + vseg * 32;
        const uint32_t sv = st + vrow * VTROWB + vseg * 64;
#pragma unroll
        for (int i = 0; i < 4; i++)
            cp16(sv + SG_VH + i*16, Vhp + gv + i*8);
    };

    {
        const size_t g = (size_t)(q0 + row) * DK_ + seg * 32;
        const uint32_t s = sb + row * QKROWB + seg * 64;
#pragma unroll
        for (int i = 0; i < 4; i++) {
            cp16(s + FQ_H + i*16, Qhp + g + i*8);
            cp16(s + FQ_L + i*16, Qlp + g + i*8);
        }
    }
    load_kv(0, 0);
    CP_COMMIT();

    float m0 = -1e30f, m1 = -1e30f, l0 = 0.f, l1 = 0.f;
    float oacc[8][4];
#pragma unroll
    for (int j = 0; j < 8; j++)
#pragma unroll
        for (int e = 0; e < 4; e++) oacc[j][e] = 0.f;

    for (int it = 0; it < 16; it++) {
        const int buf = it & 1;
        if (it < 15) {
            load_kv((it + 1) * 128, 1 - buf);
            CP_COMMIT();
            CP_WAIT(1);
        } else {
            CP_WAIT(0);
        }
        __syncthreads();
        const uint32_t st = sb + FSTG0 + (uint32_t)buf * STG_B;

        // ---- S = Q K^T (Q 2-digit, K 1-digit)
        float sacc[16][4];
#pragma unroll
        for (int j = 0; j < 16; j++)
#pragma unroll
            for (int e = 0; e < 4; e++) sacc[j][e] = 0.f;

#pragma unroll
        for (int ks = 0; ks < 4; ks++) {
            const uint32_t kb = (uint32_t)(ks * 32);
            uint32_t aH[4], aL[4];
            const uint32_t ao = sb + (warp*16 + arow) * QKROWB + acol*2 + kb;
            ldsm_x4(aH, ao + FQ_H);
            ldsm_x4(aL, ao + FQ_L);
#pragma unroll
            for (int j16 = 0; j16 < 8; j16++) {
                uint32_t bH[4];
                const uint32_t bo = st + (j16*16 + brow) * QKROWB + bcol*2 + kb;
                ldsm_x4(bH, bo + SG_KH);
#pragma unroll
                for (int hf = 0; hf < 2; hf++) {
                    float* a2 = sacc[j16*2 + hf];
                    mma_f16(a2, aH, &bH[hf*2]);
                    mma_f16(a2, aL, &bH[hf*2]);
                }
            }
        }

        // ---- mask (bitmask) + online softmax; P stays in registers
#pragma unroll
        for (int p = 0; p < 2; p++) {
            const int r  = r0 + p * 8;
            const int eb = p * 2;
            const uint4 mw = ((const uint4*)m_bits)[(size_t)(q0 + r) * 16 + it];
            const bool allset =
                (mw.x & mw.y & mw.z & mw.w) == 0xffffffffu;

            float mx = -1e30f;
            if (allset) {
#pragma unroll
                for (int j = 0; j < 16; j++) {
                    const float v0 = sacc[j][eb+0] * 0.125f;
                    const float v1 = sacc[j][eb+1] * 0.125f;
                    sacc[j][eb+0] = v0;
                    sacc[j][eb+1] = v1;
                    mx = fmaxf(mx, fmaxf(v0, v1));
                }
            } else {
                const uint32_t ws[4] = {mw.x, mw.y, mw.z, mw.w};
#pragma unroll
                for (int j = 0; j < 16; j++) {
                    const uint32_t wj = ws[j >> 2];
                    const int bit0 = (j & 3) * 8 + 2 * ln2;
                    float v0 = sacc[j][eb+0] * 0.125f;
                    float v1 = sacc[j][eb+1] * 0.125f;
                    if (!((wj >> bit0) & 1u))       v0 = -1e9f;
                    if (!((wj >> (bit0 + 1)) & 1u)) v1 = -1e9f;
                    sacc[j][eb+0] = v0;
                    sacc[j][eb+1] = v1;
                    mx = fmaxf(mx, fmaxf(v0, v1));
                }
            }
            mx = fmaxf(mx, __shfl_xor_sync(0xffffffffu, mx, 1));
            mx = fmaxf(mx, __shfl_xor_sync(0xffffffffu, mx, 2));

            const float mp   = (p == 0) ? m0 : m1;
            const float mnew = fmaxf(mp, mx);
            const float corr = __expf(mp - mnew);
            float sum = 0.f;
#pragma unroll
            for (int j = 0; j < 16; j++) {
                const float p0 = __expf(sacc[j][eb+0] - mnew);
                const float p1 = __expf(sacc[j][eb+1] - mnew);
                sacc[j][eb+0] = p0;
                sacc[j][eb+1] = p1;
                sum += p0 + p1;
            }
            sum += __shfl_xor_sync(0xffffffffu, sum, 1);
            sum += __shfl_xor_sync(0xffffffffu, sum, 2);

            if (p == 0) { l0 = l0 * corr + sum; m0 = mnew; }
            else        { l1 = l1 * corr + sum; m1 = mnew; }
#pragma unroll
            for (int j = 0; j < 8; j++) {
                oacc[j][eb+0] *= corr;
                oacc[j][eb+1] *= corr;
            }
        }

        // ---- O += P V (V 1-digit)
#pragma unroll
        for (int ks = 0; ks < 8; ks++) {
            uint32_t aP[4];
            aP[0] = pack_h2(sacc[2*ks  ][0], sacc[2*ks  ][1]);
            aP[1] = pack_h2(sacc[2*ks  ][2], sacc[2*ks  ][3]);
            aP[2] = pack_h2(sacc[2*ks+1][0], sacc[2*ks+1][1]);
            aP[3] = pack_h2(sacc[2*ks+1][2], sacc[2*ks+1][3]);
            const uint32_t kb = (uint32_t)(ks * 32);
#pragma unroll
            for (int j16 = 0; j16 < 4; j16++) {
                uint32_t bH[4];
                const uint32_t bo = st + (j16*16 + brow) * VTROWB + bcol*2 + kb;
                ldsm_x4(bH, bo + SG_VH);
                mma_f16(oacc[j16*2 + 0], aP, &bH[0]);
                mma_f16(oacc[j16*2 + 1], aP, &bH[2]);
            }
        }
        __syncthreads();
    }

    // ---- epilogue: X[b][s][h*64+dk] fp16 hi/lo
    const int bb = bh >> 4, hh = bh & 15;
#pragma unroll
    for (int p = 0; p < 2; p++) {
        const int r   = r0 + p * 8;
        const int eb  = p * 2;
        const float inv = 1.f / ((p == 0) ? l0 : l1);
        const size_t base = ((size_t)(bb * S_ + q0 + r)) * D_ + hh * DK_ + 2*ln2;
#pragma unroll
        for (int j = 0; j < 8; j++) {
            uint32_t hp, lp;
            split_pack2(oacc[j][eb+0] * inv, oacc[j][eb+1] * inv, hp, lp);
            *(uint32_t*)(x_h + base + j*8) = hp;
            *(uint32_t*)(x_l + base + j*8) = lp;
        }
    }
}

// ---------------------------------------------------------------------------
extern "C" void kernel_launch(void* const* d_in, const int* in_sizes, int n_in,
                              void* d_out, int out_size)
{
    (void)in_sizes; (void)n_in; (void)out_size;
    const float* query = (const float*)d_in[0];
    const float* key_  = (const float*)d_in[1];
    const float* value = (const float*)d_in[2];
    const int*   mask  = (const int*)  d_in[3];
    const float* Wq    = (const float*)d_in[4];
    const float* bq    = (const float*)d_in[5];
    const float* Wk    = (const float*)d_in[6];
    const float* bk    = (const float*)d_in[7];
    const float* Wv    = (const float*)d_in[8];
    const float* bv    = (const float*)d_in[9];
    const float* Wo    = (const float*)d_in[10];
    const float* bo    = (const float*)d_in[11];
    float* out = (float*)d_out;

    cudaFuncSetAttribute(flash_mma_kernel,
                         cudaFuncAttributeMaxDynamicSharedMemorySize, F_SMEM);
    cudaFuncSetAttribute(gemm_qkv_kernel,
                         cudaFuncAttributeMaxDynamicSharedMemorySize, GSMEM);
    cudaFuncSetAttribute(gemm_out_kernel,
                         cudaFuncAttributeMaxDynamicSharedMemorySize, GSMEM);

    void *cqh,*cql,*ckh,*ckl,*cvh,*cvl;
    void *wqh,*wql,*wkh,*wkl,*wvh,*wvl,*woh,*wol;
    void *pqh,*pql,*pkh,*pkl,*pvth,*pvtl,*xh,*xl;
    cudaGetSymbolAddress(&cqh, c_qh); cudaGetSymbolAddress(&cql, c_ql);
    cudaGetSymbolAddress(&ckh, c_kh); cudaGetSymbolAddress(&ckl, c_kl);
    cudaGetSymbolAddress(&cvh, c_vh); cudaGetSymbolAddress(&cvl, c_vl);
    cudaGetSymbolAddress(&wqh, w_qh); cudaGetSymbolAddress(&wql, w_ql);
    cudaGetSymbolAddress(&wkh, w_kh); cudaGetSymbolAddress(&wkl, w_kl);
    cudaGetSymbolAddress(&wvh, w_vh); cudaGetSymbolAddress(&wvl, w_vl);
    cudaGetSymbolAddress(&woh, w_oh); cudaGetSymbolAddress(&wol, w_ol);
    cudaGetSymbolAddress(&pqh, p_qh); cudaGetSymbolAddress(&pql, p_ql);
    cudaGetSymbolAddress(&pkh, p_kh); cudaGetSymbolAddress(&pkl, p_kl);
    cudaGetSymbolAddress(&pvth, p_vth); cudaGetSymbolAddress(&pvtl, p_vtl);
    cudaGetSymbolAddress(&xh, x_h); cudaGetSymbolAddress(&xl, x_l);

    typedef unsigned short us;

    // 1) fused convert
    CvtArgs ca;
    ca.in[0] = query; ca.hi[0] = (us*)cqh; ca.lo[0] = (us*)cql;
    ca.in[1] = key_;  ca.hi[1] = (us*)ckh; ca.lo[1] = (us*)ckl;
    ca.in[2] = value; ca.hi[2] = (us*)cvh; ca.lo[2] = (us*)cvl;
    ca.in[3] = Wq;    ca.hi[3] = (us*)wqh; ca.lo[3] = (us*)wql;
    ca.in[4] = Wk;    ca.hi[4] = (us*)wkh; ca.lo[4] = (us*)wkl;
    ca.in[5] = Wv;    ca.hi[5] = (us*)wvh; ca.lo[5] = (us*)wvl;
    ca.in[6] = Wo;    ca.hi[6] = (us*)woh; ca.lo[6] = (us*)wol;
    convert_all_kernel<<<dim3(512, 7), 256>>>(ca, M_*D_/4, D_*D_/4);

    // 2) mask bitmask
    mask_bits_kernel<<<S_*S_/32/256, 256>>>(mask);

    // 3) fused Q/K/V projections (one launch, z = 3)
    QKVArgs qa;
    qa.Ah[0] = (const us*)cqh; qa.Al[0] = (const us*)cql;
    qa.Wh[0] = (const us*)wqh; qa.Wl[0] = (const us*)wql;
    qa.bias[0] = bq; qa.outh[0] = (us*)pqh; qa.outl[0] = (us*)pql;
    qa.Ah[1] = (const us*)ckh; qa.Al[1] = (const us*)ckl;
    qa.Wh[1] = (const us*)wkh; qa.Wl[1] = (const us*)wkl;
    qa.bias[1] = bk; qa.outh[1] = (us*)pkh; qa.outl[1] = (us*)pkl;
    qa.Ah[2] = (const us*)cvh; qa.Al[2] = (const us*)cvl;
    qa.Wh[2] = (const us*)wvh; qa.Wl[2] = (const us*)wvl;
    qa.bias[2] = bv; qa.outh[2] = (us*)pvth; qa.outl[2] = (us*)pvtl;
    gemm_qkv_kernel<<<dim3(D_/128, M_/128, 3), 256, GSMEM>>>(qa);

    // 4) flash attention (2 CTAs/SM)
    flash_mma_kernel<<<dim3(S_/128, B_*H_), 256, F_SMEM>>>();

    // 5) output projection
    gemm_out_kernel<<<dim3(D_/128, M_/128), 256, GSMEM>>>(
        (const us*)xh, (const us*)xl, (const us*)woh, (const us*)wol,
        bo, out);
}